// round 4
// baseline (speedup 1.0000x reference)
#include <cuda_runtime.h>
#include <cuda_bf16.h>

// Problem constants (fixed by the dataset)
#define B_TOT   1024
#define S_LEN   2048
#define F_IN    9
#define NOUT    8
#define UDIM    256
#define LBK     3
#define DDIM    11      // NOUT + 3
#define XDIM    33      // LBK * DDIM
#define H1DIM   512     // 2*U
#define T_OUT   2044    // S - 1 - LBK
#define M_ROWS  8
#define NCTA    128     // NCTA * M_ROWS == B_TOT
#define NTHREADS 256

__global__ __launch_bounds__(NTHREADS, 1)
void dps_kernel(const float* __restrict__ inputs,
                const float* __restrict__ ln1_g, const float* __restrict__ ln1_b,
                const float* __restrict__ w1,    const float* __restrict__ b1,
                const float* __restrict__ w2,    const float* __restrict__ b2,
                const float* __restrict__ wu,    const float* __restrict__ bu,
                const float* __restrict__ ln2_g, const float* __restrict__ ln2_b,
                const float* __restrict__ wbeta,
                const float* __restrict__ wd1,   const float* __restrict__ bd1,
                const float* __restrict__ wd2,   const float* __restrict__ bd2,
                const int*   __restrict__ fix,
                float* __restrict__ out)
{
    __shared__ float s_win[M_ROWS][LBK][NOUT];     // rolling window
    __shared__ float s_xx [M_ROWS][XDIM];          // post-LN1 flattened input
    __shared__ float s_big[M_ROWS][H1DIM];         // h1 (enc) then t1 (dec) - aliased
    __shared__ float s_h  [M_ROWS][UDIM];          // encoder output
    __shared__ float s_comb[M_ROWS][260];          // [0..255]=st (after LN2), [256]=ect; padded to 16B
    __shared__ float s_y  [M_ROWS][NOUT];

    const int tid  = threadIdx.x;
    const int lane = tid & 31;
    const int wid  = tid >> 5;
    const int row0 = blockIdx.x * M_ROWS;

    const int fix0 = fix[0];
    const int fix1 = fix[1];

    // ---- init window: win[m][t][n] = inputs[row0+m, t, 1+n]
    for (int idx = tid; idx < M_ROWS * LBK * NOUT; idx += NTHREADS) {
        int m = idx / (LBK * NOUT);
        int r = idx % (LBK * NOUT);
        int t = r / NOUT, n = r % NOUT;
        s_win[m][t][n] = inputs[((size_t)(row0 + m) * S_LEN + t) * F_IN + 1 + n];
    }
    __syncthreads();

    for (int i = LBK; i < S_LEN - 1; ++i) {
        // ================= Phase A: build x (lc + win), LayerNorm1 =================
        if (tid < M_ROWS * LBK) {
            int m = tid / LBK, t = tid % LBK;
            int s = i - LBK + t;
            size_t base = ((size_t)(row0 + m) * S_LEN + s) * F_IN;
            float ld = inputs[base];
            float df = (s > 0) ? (ld - inputs[base - F_IN]) : 0.0f;
            float x[DDIM];
            x[0] = ld; x[1] = ld; x[2] = df;   // loading, integral(=cumsum over size-1 axis), diff
            #pragma unroll
            for (int n = 0; n < NOUT; ++n) x[3 + n] = s_win[m][t][n];
            float mean = 0.f;
            #pragma unroll
            for (int d = 0; d < DDIM; ++d) mean += x[d];
            mean *= (1.0f / DDIM);
            float var = 0.f;
            #pragma unroll
            for (int d = 0; d < DDIM; ++d) { float c = x[d] - mean; var += c * c; }
            var *= (1.0f / DDIM);
            float rs = rsqrtf(var + 1e-3f);
            #pragma unroll
            for (int d = 0; d < DDIM; ++d)
                s_xx[m][t * DDIM + d] = (x[d] - mean) * rs * ln1_g[d] + ln1_b[d];
        }
        __syncthreads();

        // ================= Phase B: enc1 (33 -> 512) + tanh ========================
        {
            float acc0[M_ROWS], acc1[M_ROWS];
            #pragma unroll
            for (int m = 0; m < M_ROWS; ++m) { acc0[m] = 0.f; acc1[m] = 0.f; }
            const int j0 = tid, j1 = tid + 256;
            #pragma unroll 3
            for (int k = 0; k < XDIM; ++k) {
                float wa = w1[k * H1DIM + j0];
                float wb = w1[k * H1DIM + j1];
                #pragma unroll
                for (int m = 0; m < M_ROWS; ++m) {
                    float xv = s_xx[m][k];
                    acc0[m] = fmaf(xv, wa, acc0[m]);
                    acc1[m] = fmaf(xv, wb, acc1[m]);
                }
            }
            float ba = b1[j0], bb = b1[j1];
            #pragma unroll
            for (int m = 0; m < M_ROWS; ++m) {
                s_big[m][j0] = tanhf(acc0[m] + ba);
                s_big[m][j1] = tanhf(acc1[m] + bb);
            }
        }
        __syncthreads();

        // ================= Phase C: enc2 (512 -> 256) ==============================
        {
            float acc[M_ROWS];
            #pragma unroll
            for (int m = 0; m < M_ROWS; ++m) acc[m] = 0.f;
            const int j = tid;
            #pragma unroll 2
            for (int k = 0; k < H1DIM; k += 4) {
                float wv0 = w2[(k + 0) * UDIM + j];
                float wv1 = w2[(k + 1) * UDIM + j];
                float wv2 = w2[(k + 2) * UDIM + j];
                float wv3 = w2[(k + 3) * UDIM + j];
                #pragma unroll
                for (int m = 0; m < M_ROWS; ++m) {
                    float4 hv = *reinterpret_cast<const float4*>(&s_big[m][k]);
                    acc[m] = fmaf(hv.x, wv0, acc[m]);
                    acc[m] = fmaf(hv.y, wv1, acc[m]);
                    acc[m] = fmaf(hv.z, wv2, acc[m]);
                    acc[m] = fmaf(hv.w, wv3, acc[m]);
                }
            }
            float bb = b2[j];
            #pragma unroll
            for (int m = 0; m < M_ROWS; ++m) s_h[m][j] = acc[m] + bb;
        }
        __syncthreads();

        // ================= Phase D: upd (256 -> 256) + beta reduction ==============
        {
            float acc[M_ROWS];
            #pragma unroll
            for (int m = 0; m < M_ROWS; ++m) acc[m] = 0.f;
            const int j = tid;
            #pragma unroll 2
            for (int k = 0; k < UDIM; k += 4) {
                float wv0 = wu[(k + 0) * UDIM + j];
                float wv1 = wu[(k + 1) * UDIM + j];
                float wv2 = wu[(k + 2) * UDIM + j];
                float wv3 = wu[(k + 3) * UDIM + j];
                #pragma unroll
                for (int m = 0; m < M_ROWS; ++m) {
                    float4 hv = *reinterpret_cast<const float4*>(&s_h[m][k]);
                    acc[m] = fmaf(hv.x, wv0, acc[m]);
                    acc[m] = fmaf(hv.y, wv1, acc[m]);
                    acc[m] = fmaf(hv.z, wv2, acc[m]);
                    acc[m] = fmaf(hv.w, wv3, acc[m]);
                }
            }
            float bb = bu[j];
            #pragma unroll
            for (int m = 0; m < M_ROWS; ++m) s_comb[m][j] = acc[m] + bb;   // pre-LN u
        }
        {   // ect[m] = h[m] . beta_w   (one warp per row)
            int m = wid;
            float p = 0.f;
            for (int k = lane; k < UDIM; k += 32) p = fmaf(s_h[m][k], wbeta[k], p);
            #pragma unroll
            for (int o = 16; o > 0; o >>= 1) p += __shfl_xor_sync(0xffffffffu, p, o);
            if (lane == 0) s_comb[m][UDIM] = p;
        }
        __syncthreads();

        // ================= Phase E: LayerNorm2 over 256 (one warp per row) =========
        {
            int m = wid;
            float v[8];
            float4 a = *reinterpret_cast<const float4*>(&s_comb[m][lane * 8]);
            float4 b = *reinterpret_cast<const float4*>(&s_comb[m][lane * 8 + 4]);
            v[0]=a.x; v[1]=a.y; v[2]=a.z; v[3]=a.w;
            v[4]=b.x; v[5]=b.y; v[6]=b.z; v[7]=b.w;
            float sum = 0.f, sq = 0.f;
            #pragma unroll
            for (int q = 0; q < 8; ++q) { sum += v[q]; sq = fmaf(v[q], v[q], sq); }
            #pragma unroll
            for (int o = 16; o > 0; o >>= 1) {
                sum += __shfl_xor_sync(0xffffffffu, sum, o);
                sq  += __shfl_xor_sync(0xffffffffu, sq, o);
            }
            float mean = sum * (1.0f / UDIM);
            float var  = sq * (1.0f / UDIM) - mean * mean;
            float rs = rsqrtf(var + 1e-3f);
            #pragma unroll
            for (int q = 0; q < 8; ++q) {
                int k = lane * 8 + q;
                s_comb[m][k] = (v[q] - mean) * rs * ln2_g[k] + ln2_b[k];
            }
        }
        __syncthreads();

        // ================= Phase F: dec1 (257 -> 512) + tanh =======================
        {
            float acc0[M_ROWS], acc1[M_ROWS];
            #pragma unroll
            for (int m = 0; m < M_ROWS; ++m) { acc0[m] = 0.f; acc1[m] = 0.f; }
            const int j0 = tid, j1 = tid + 256;
            #pragma unroll 4
            for (int k = 0; k < UDIM + 1; ++k) {
                float wa = wd1[k * H1DIM + j0];
                float wb = wd1[k * H1DIM + j1];
                #pragma unroll
                for (int m = 0; m < M_ROWS; ++m) {
                    float cv = s_comb[m][k];
                    acc0[m] = fmaf(cv, wa, acc0[m]);
                    acc1[m] = fmaf(cv, wb, acc1[m]);
                }
            }
            float ba = bd1[j0], bb = bd1[j1];
            #pragma unroll
            for (int m = 0; m < M_ROWS; ++m) {
                s_big[m][j0] = tanhf(acc0[m] + ba);   // t1 (aliases h1; synced since)
                s_big[m][j1] = tanhf(acc1[m] + bb);
            }
        }
        __syncthreads();

        // ================= Phase G: dec2 (512 -> 8), fix override, output ==========
        {
            int m = wid;
            int n = lane & 7;
            int c = lane >> 3;            // 4 chunks of 128
            float acc = 0.f;
            int k0 = c * 128;
            #pragma unroll 4
            for (int k = k0; k < k0 + 128; ++k)
                acc = fmaf(s_big[m][k], wd2[k * NOUT + n], acc);
            acc += __shfl_down_sync(0xffffffffu, acc, 16);
            acc += __shfl_down_sync(0xffffffffu, acc, 8);
            if (lane < 8) {
                float y = acc + bd2[n];
                int b = row0 + m;
                size_t ib = ((size_t)b * S_LEN + (i + 1)) * F_IN;
                if (n == fix0) y = inputs[ib + 1 + fix0];
                if (n == fix1) y = inputs[ib + 1 + fix1];
                s_y[m][n] = y;
                // out shape (NOUT, B, T): out[n, b, t]
                out[(size_t)n * ((size_t)B_TOT * T_OUT) + (size_t)b * T_OUT + (i - LBK)] = y;
            }
        }
        __syncthreads();

        // ---- window shift (each thread owns one (m, n): read-then-write safe)
        if (tid < M_ROWS * NOUT) {
            int m = tid >> 3, n = tid & 7;
            float a = s_win[m][1][n];
            float b = s_win[m][2][n];
            s_win[m][0][n] = a;
            s_win[m][1][n] = b;
            s_win[m][2][n] = s_y[m][n];
        }
        __syncthreads();
    }
}

extern "C" void kernel_launch(void* const* d_in, const int* in_sizes, int n_in,
                              void* d_out, int out_size) {
    const float* inputs = (const float*)d_in[0];
    const float* ln1_g  = (const float*)d_in[1];
    const float* ln1_b  = (const float*)d_in[2];
    const float* w1     = (const float*)d_in[3];
    const float* b1     = (const float*)d_in[4];
    const float* w2     = (const float*)d_in[5];
    const float* b2     = (const float*)d_in[6];
    const float* wu     = (const float*)d_in[7];
    const float* bu     = (const float*)d_in[8];
    const float* ln2_g  = (const float*)d_in[9];
    const float* ln2_b  = (const float*)d_in[10];
    const float* wbeta  = (const float*)d_in[11];
    const float* wd1    = (const float*)d_in[12];
    const float* bd1    = (const float*)d_in[13];
    const float* wd2    = (const float*)d_in[14];
    const float* bd2    = (const float*)d_in[15];
    const int*   fix    = (const int*)  d_in[16];
    float* out = (float*)d_out;

    dps_kernel<<<NCTA, NTHREADS>>>(inputs, ln1_g, ln1_b, w1, b1, w2, b2,
                                   wu, bu, ln2_g, ln2_b, wbeta,
                                   wd1, bd1, wd2, bd2, fix, out);
}